// round 16
// baseline (speedup 1.0000x reference)
#include <cuda_runtime.h>
#include <cuda_bf16.h>
#include <cuda_fp16.h>
#include <math.h>
#include <stdint.h>

#define N_NODES 50000
#define N_PAD   50048            // 391 * 128
#define N_EDGES 800000
#define N_BATCH 128
#define D_IN    15
#define D_HID   256
#define D_OUT   128
#define LN_EPS  1e-5f
#define NB_SCAN 49               // ceil(50000/1024)

// ---------------- device scratch -------------------------------------------
// Activation rows: 512 fp16 = [mean(0:256) | x(256:512)]
__device__ __half g_AA[(size_t)N_PAD * 512];          // 51 MB
__device__ __half g_AB[(size_t)N_PAD * 512];          // 51 MB
__device__ __half g_WtAll[(256 + 256 + 128) * 512];   // W^T fp16, layers 2,3,4
__device__ __half g_xc16[(size_t)N_PAD * 64];         // layer-1 fp16 concat (K=64)
__device__ __half g_Wt1[256 * 64];                    // layer-1 W^T fp16
__device__ int   g_ssrc[N_EDGES];
__device__ int   g_off [N_NODES + 1];
__device__ int   g_cur [N_NODES];
__device__ int   g_deg [N_NODES];                     // self-cleaned in k_scan
__device__ int   g_bsum[64];
__device__ int   g_bcnt[N_BATCH];                     // self-cleaned in k_scan
__device__ float g_binv[N_BATCH];                     // 1/count per batch
__device__ unsigned int g_epoch;                      // monotonic barrier counter

// ---------------- PTX helpers ----------------------------------------------
__device__ __forceinline__ uint32_t smem_to_u32(const void* p) {
    uint32_t a;
    asm("{ .reg .u64 t; cvta.to.shared.u64 t, %1; cvt.u32.u64 %0, t; }" : "=r"(a) : "l"(p));
    return a;
}
#define CP16(dst, src) \
    asm volatile("cp.async.cg.shared.global [%0], [%1], 16;" :: "r"((uint32_t)(dst)), "l"(src) : "memory")
#define CP_COMMIT() asm volatile("cp.async.commit_group;" ::: "memory")
#define CP_WAIT(n)  asm volatile("cp.async.wait_group %0;" :: "n"(n) : "memory")
#define SWZ(b) ((b) ^ (((b) >> 3) & 0x70))
#define LDSM_X4(r0, r1, r2, r3, addr) \
    asm volatile("ldmatrix.sync.aligned.m8n8.x4.shared.b16 {%0,%1,%2,%3}, [%4];" \
                 : "=r"(r0), "=r"(r1), "=r"(r2), "=r"(r3) : "r"(addr))
#define MMA_F16(d, a, b0, b1) \
    asm volatile("mma.sync.aligned.m16n8k16.row.col.f32.f16.f16.f32 " \
                 "{%0,%1,%2,%3}, {%4,%5,%6,%7}, {%8,%9}, {%0,%1,%2,%3};" \
                 : "+f"((d)[0]), "+f"((d)[1]), "+f"((d)[2]), "+f"((d)[3]) \
                 : "r"((a)[0]), "r"((a)[1]), "r"((a)[2]), "r"((a)[3]), \
                   "r"(b0), "r"(b1))

// ---------------- setup kernels --------------------------------------------
// histograms (4 edges/thread for atomic MLP) + zero out
__global__ void k_hist(const int* __restrict__ dst, const int* __restrict__ batch,
                       float* __restrict__ out) {
    int i = blockIdx.x * blockDim.x + threadIdx.x;
    int e0 = i * 4;
    if (e0 + 3 < N_EDGES) {
        int d0 = dst[e0], d1 = dst[e0 + 1], d2 = dst[e0 + 2], d3 = dst[e0 + 3];
        atomicAdd(&g_deg[d0], 1);
        atomicAdd(&g_deg[d1], 1);
        atomicAdd(&g_deg[d2], 1);
        atomicAdd(&g_deg[d3], 1);
    } else {
        for (int e = e0; e < N_EDGES; e++) atomicAdd(&g_deg[dst[e]], 1);
    }
    if (i < N_NODES) atomicAdd(&g_bcnt[batch[i]], 1);
    if (i < N_BATCH * D_OUT) out[i] = 0.f;
}

// merged scan: per-block scan + epoch-counter grid barrier + global prefix
// grid = 49 blocks (all co-resident on 148 SMs -> spin is deadlock-free)
__global__ void k_scan() {
    __shared__ int ws[32];
    __shared__ int sexcl;
    int tid = threadIdx.x, lane = tid & 31, wid = tid >> 5;
    int i = blockIdx.x * 1024 + tid;

    // ---- per-block exclusive scan of deg (+ self-clean) ----
    int v = 0;
    if (i < N_NODES) { v = g_deg[i]; g_deg[i] = 0; }
    int x = v;
    #pragma unroll
    for (int o = 1; o < 32; o <<= 1) {
        int t = __shfl_up_sync(0xffffffffu, x, o);
        if (lane >= o) x += t;
    }
    if (lane == 31) ws[wid] = x;
    __syncthreads();
    if (wid == 0) {
        int y = ws[lane];
        #pragma unroll
        for (int o = 1; o < 32; o <<= 1) {
            int t = __shfl_up_sync(0xffffffffu, y, o);
            if (lane >= o) y += t;
        }
        ws[lane] = y;
    }
    __syncthreads();
    int incl = x + (wid ? ws[wid - 1] : 0);
    int btotal = ws[31];                       // block total (all warps see it)
    if (tid == 1023) {
        g_bsum[blockIdx.x] = btotal;
        __threadfence();
    }
    __syncthreads();

    // ---- epoch-counter grid barrier (monotonic; replay-safe) ----
    if (tid == 0) {
        unsigned t = atomicAdd(&g_epoch, 1u);
        unsigned target = (t / NB_SCAN + 1u) * NB_SCAN;
        while (atomicAdd(&g_epoch, 0u) < target) { }
        __threadfence();
    }
    __syncthreads();

    // ---- exclusive prefix of the 49 block totals (warp 0) ----
    if (tid < 32) {
        int bv = (lane < NB_SCAN) ? g_bsum[lane] : 0;
        int bx = bv;
        #pragma unroll
        for (int o = 1; o < 32; o <<= 1) {
            int t = __shfl_up_sync(0xffffffffu, bx, o);
            if (lane >= o) bx += t;
        }
        int excl = bx - bv;
        int myexcl;
        if (blockIdx.x < 32) {
            myexcl = __shfl_sync(0xffffffffu, excl, blockIdx.x);
        } else {
            int base = __shfl_sync(0xffffffffu, bx, 31);
            int a = base;
            for (int b = 32; b < (int)blockIdx.x; b++) a += g_bsum[b];
            myexcl = a;
        }
        if (lane == 0) {
            sexcl = myexcl;
            if (blockIdx.x == NB_SCAN - 1) g_off[N_NODES] = myexcl + btotal;
        }
    }
    // block 0: batch inverse counts + bcnt self-clean (bcnt final since k_hist)
    if (blockIdx.x == 0 && tid >= 128 && tid < 256) {
        int b = tid - 128;
        int c = g_bcnt[b];
        g_binv[b] = 1.f / (float)max(c, 1);
        g_bcnt[b] = 0;
    }
    __syncthreads();
    if (i < N_NODES) {
        int o = (incl - v) + sexcl;
        g_off[i] = o;
        g_cur[i] = o;
    }
}

// counting-sort scatter (1 edge/thread — measured fastest) + weight build
__global__ void k_scatterW(const int* __restrict__ src, const int* __restrict__ dst,
                           const float* __restrict__ Wl1, const float* __restrict__ Wr1,
                           const float* __restrict__ Wl2, const float* __restrict__ Wr2,
                           const float* __restrict__ Wl3, const float* __restrict__ Wr3,
                           const float* __restrict__ Wl4, const float* __restrict__ Wr4) {
    int e = blockIdx.x * blockDim.x + threadIdx.x;
    if (e < N_EDGES) {
        int p = atomicAdd(&g_cur[dst[e]], 1);
        g_ssrc[p] = src[e];
    }
    if (e < 344064) {
        int i = e;
        if (i < 16384) {                                 // Wt1 [256][64]
            int n = i >> 6, k = i & 63;
            float v = 0.f;
            if (k < D_IN)          v = Wl1[k * D_HID + n];
            else if (k < 2 * D_IN) v = Wr1[(k - D_IN) * D_HID + n];
            g_Wt1[i] = __float2half(v);
        } else {
            i -= 16384;
            const float *Wl, *Wr;
            __half* Wt;
            int ncols;
            if (i < 131072)      { Wl = Wl2; Wr = Wr2; Wt = g_WtAll;                     ncols = D_HID; }
            else if (i < 262144) { Wl = Wl3; Wr = Wr3; Wt = g_WtAll + (size_t)256 * 512; ncols = D_HID; i -= 131072; }
            else                 { Wl = Wl4; Wr = Wr4; Wt = g_WtAll + (size_t)512 * 512; ncols = D_OUT; i -= 262144; }
            int n = i / 512, k = i - n * 512;
            float v = (k < 256) ? Wl[k * ncols + n] : Wr[(k - 256) * ncols + n];
            Wt[n * 512 + k] = __float2half(v);
        }
    }
}

// ---------------- layer-1 concat build (fp16, K=64 padded), 4-way unrolled ---
__global__ void k_agg15h(const float* __restrict__ x, __half* __restrict__ xc) {
    int warp = (blockIdx.x * blockDim.x + threadIdx.x) >> 5;
    if (warp >= N_NODES) return;
    int lane = threadIdx.x & 31;
    int s = g_off[warp], e = g_off[warp + 1];
    float acc = 0.f;
    int i = s;
    for (; i + 3 < e; i += 4) {
        int s0 = g_ssrc[i], s1 = g_ssrc[i + 1], s2 = g_ssrc[i + 2], s3 = g_ssrc[i + 3];
        float v0 = 0.f, v1 = 0.f, v2 = 0.f, v3 = 0.f;
        if (lane < D_IN) {
            v0 = x[s0 * D_IN + lane];
            v1 = x[s1 * D_IN + lane];
            v2 = x[s2 * D_IN + lane];
            v3 = x[s3 * D_IN + lane];
        }
        acc += (v0 + v1) + (v2 + v3);
    }
    for (; i < e; i++) {
        int sn = g_ssrc[i];
        if (lane < D_IN) acc += x[sn * D_IN + lane];
    }
    float inv = 1.f / (float)max(e - s, 1);
    __half* row = xc + (size_t)warp * 64;
    if (lane < D_IN) {
        row[lane]        = __float2half(acc * inv);
        row[D_IN + lane] = __float2half(x[warp * D_IN + lane]);
    }
}

// ---------------- mean aggregation ------------------------------------------
__device__ __forceinline__ void acch(float* a, uint4 h) {
    const __half2* hp = (const __half2*)&h;
    #pragma unroll
    for (int p = 0; p < 4; p++) {
        float2 f = __half22float2(hp[p]);
        a[2 * p]     += f.x;
        a[2 * p + 1] += f.y;
    }
}
__global__ void k_aggmean(const __half* __restrict__ Ain, __half* __restrict__ Am) {
    int warp = (blockIdx.x * blockDim.x + threadIdx.x) >> 5;
    if (warp >= N_NODES) return;
    int lane = threadIdx.x & 31;
    int s = g_off[warp], e = g_off[warp + 1];
    float acc[8];
    #pragma unroll
    for (int j = 0; j < 8; j++) acc[j] = 0.f;
    int i = s;
    for (; i + 7 < e; i += 8) {
        uint4 v[8];
        #pragma unroll
        for (int u = 0; u < 8; u++) {
            int sn = g_ssrc[i + u];
            v[u] = *(const uint4*)(Ain + (size_t)sn * 512 + 256 + lane * 8);
        }
        #pragma unroll
        for (int u = 0; u < 8; u++) acch(acc, v[u]);
    }
    for (; i + 3 < e; i += 4) {
        uint4 v[4];
        #pragma unroll
        for (int u = 0; u < 4; u++) {
            int sn = g_ssrc[i + u];
            v[u] = *(const uint4*)(Ain + (size_t)sn * 512 + 256 + lane * 8);
        }
        #pragma unroll
        for (int u = 0; u < 4; u++) acch(acc, v[u]);
    }
    for (; i < e; i++) {
        int sn = g_ssrc[i];
        uint4 v = *(const uint4*)(Ain + (size_t)sn * 512 + 256 + lane * 8);
        acch(acc, v);
    }
    float inv = 1.f / (float)max(e - s, 1);
    __half2 o[4];
    #pragma unroll
    for (int p = 0; p < 4; p++)
        o[p] = __floats2half2_rn(acc[2 * p] * inv, acc[2 * p + 1] * inv);
    *(uint4*)(Am + (size_t)warp * 512 + lane * 8) = *(uint4*)o;
}

// ---------------- fused fp16 tensor-core GEMM + bias + LN + GELU -------------
// K = NC*64, 3-stage cp.async pipeline. BM=128, BN=NT, 512 threads (16 warps 4m x 4n)
// MODE 0: write x-half fp16 into Anext.  MODE 1: pre-scaled pool atomics.
template<int NT, int MODE, int NC>
__global__ __launch_bounds__(512)
void k_gemm_f(const __half* __restrict__ A, const __half* __restrict__ Wt,
              const float* __restrict__ bias, const float* __restrict__ gam,
              const float* __restrict__ bet, __half* __restrict__ Anext,
              float* __restrict__ out, const int* __restrict__ batch) {
    extern __shared__ char smem[];
    uint32_t sb = smem_to_u32(smem);
    constexpr int K = NC * 64;
    constexpr int BBYTES = NT * 128;
    constexpr int STAGE = 16384 + BBYTES;
    constexpr int NSTG = (NC >= 3) ? 3 : ((NC >= 2) ? 2 : 1);
    constexpr int NB = NT / 32;
    constexpr int NB4 = NT / 64;
    constexpr int BAND = NT / 4;
    float2* red = (float2*)(smem + NSTG * STAGE);

    int tid = threadIdx.x, lane = tid & 31, warp = tid >> 5;
    int warp_m = warp & 3, warp_n = warp >> 2;
    int row0 = blockIdx.x * 128;

    float acc[2][NB][4];
    #pragma unroll
    for (int mi = 0; mi < 2; mi++)
        #pragma unroll
        for (int nb = 0; nb < NB; nb++)
            #pragma unroll
            for (int r = 0; r < 4; r++) acc[mi][nb][r] = 0.f;

    auto issue = [&](int c, int s) {
        uint32_t dA = sb + s * STAGE;
        uint32_t dB = dA + 16384;
        const __half* pa = A + (size_t)row0 * K + c * 64;
        const __half* pb = Wt + c * 64;
        #pragma unroll
        for (int i = 0; i < 2; i++) {
            int t = tid + i * 512;
            int r = t >> 3, seg = t & 7;
            CP16(dA + SWZ(r * 128 + seg * 16), pa + (size_t)r * K + seg * 8);
        }
        #pragma unroll
        for (int i = 0; i < NB4; i++) {
            int t = tid + i * 512;
            int r = t >> 3, seg = t & 7;
            CP16(dB + SWZ(r * 128 + seg * 16), pb + (size_t)r * K + seg * 8);
        }
        CP_COMMIT();
    };

    issue(0, 0);
    if (NC > 1) issue(1, 1 % NSTG);
    for (int c = 0; c < NC; c++) {
        int s = c % NSTG;
        if (c + 2 < NC) { issue(c + 2, (c + 2) % NSTG); CP_WAIT(2); }
        else if (c + 1 < NC) { CP_WAIT(1); }
        else { CP_WAIT(0); }
        __syncthreads();
        uint32_t sA = sb + s * STAGE, sB = sA + 16384;
        #pragma unroll
        for (int kk = 0; kk < 64; kk += 16) {
            uint32_t a[2][4], b[NB4][4];
            #pragma unroll
            for (int mi = 0; mi < 2; mi++) {
                int r = warp_m * 32 + mi * 16 + (lane & 15);
                int cb = (kk + (lane >> 4) * 8) * 2;
                LDSM_X4(a[mi][0], a[mi][1], a[mi][2], a[mi][3], sA + SWZ(r * 128 + cb));
            }
            #pragma unroll
            for (int nb4 = 0; nb4 < NB4; nb4++) {
                int g = lane >> 3;
                int n = warp_n * BAND + nb4 * 16 + (lane & 7) + (g >> 1) * 8;
                int kb = (kk + (g & 1) * 8) * 2;
                LDSM_X4(b[nb4][0], b[nb4][1], b[nb4][2], b[nb4][3], sB + SWZ(n * 128 + kb));
            }
            #pragma unroll
            for (int mi = 0; mi < 2; mi++)
                #pragma unroll
                for (int nb = 0; nb < NB; nb++) {
                    uint32_t b0 = b[nb >> 1][(nb & 1) * 2];
                    uint32_t b1 = b[nb >> 1][(nb & 1) * 2 + 1];
                    MMA_F16(acc[mi][nb], a[mi], b0, b1);
                }
        }
        __syncthreads();
    }

    // ---- epilogue: bias + LN + GELU + output ----
    int tr = lane >> 2, tc = lane & 3;
    #pragma unroll
    for (int nb = 0; nb < NB; nb++) {
        int cg = warp_n * BAND + nb * 8 + tc * 2;
        float bx = bias[cg], by = bias[cg + 1];
        #pragma unroll
        for (int mi = 0; mi < 2; mi++) {
            acc[mi][nb][0] += bx; acc[mi][nb][1] += by;
            acc[mi][nb][2] += bx; acc[mi][nb][3] += by;
        }
    }
    float ss[2][2], qq[2][2];
    #pragma unroll
    for (int mi = 0; mi < 2; mi++)
        #pragma unroll
        for (int h = 0; h < 2; h++) {
            float s = 0.f, q = 0.f;
            #pragma unroll
            for (int nb = 0; nb < NB; nb++) {
                float v0 = acc[mi][nb][2 * h], v1 = acc[mi][nb][2 * h + 1];
                s += v0 + v1; q += v0 * v0 + v1 * v1;
            }
            s += __shfl_xor_sync(0xffffffffu, s, 1);
            q += __shfl_xor_sync(0xffffffffu, q, 1);
            s += __shfl_xor_sync(0xffffffffu, s, 2);
            q += __shfl_xor_sync(0xffffffffu, q, 2);
            ss[mi][h] = s; qq[mi][h] = q;
        }
    if (tc == 0) {
        #pragma unroll
        for (int mi = 0; mi < 2; mi++)
            #pragma unroll
            for (int h = 0; h < 2; h++)
                red[warp_n * 128 + warp_m * 32 + mi * 16 + h * 8 + tr] =
                    make_float2(ss[mi][h], qq[mi][h]);
    }
    __syncthreads();
    float mean_[2][2], rstd[2][2];
    #pragma unroll
    for (int mi = 0; mi < 2; mi++)
        #pragma unroll
        for (int h = 0; h < 2; h++) {
            int rloc = warp_m * 32 + mi * 16 + h * 8 + tr;
            float S = 0.f, Q = 0.f;
            #pragma unroll
            for (int wn = 0; wn < 4; wn++) {
                float2 p = red[wn * 128 + rloc];
                S += p.x; Q += p.y;
            }
            float mu = S * (1.f / NT);
            float var = fmaxf(Q * (1.f / NT) - mu * mu, 0.f);
            mean_[mi][h] = mu;
            rstd[mi][h] = rsqrtf(var + LN_EPS);
        }
    #pragma unroll
    for (int nb = 0; nb < NB; nb++) {
        int cg = warp_n * BAND + nb * 8 + tc * 2;
        float g0 = gam[cg], g1 = gam[cg + 1];
        float t0 = bet[cg], t1 = bet[cg + 1];
        #pragma unroll
        for (int mi = 0; mi < 2; mi++)
            #pragma unroll
            for (int h = 0; h < 2; h++) {
                int rg = row0 + warp_m * 32 + mi * 16 + h * 8 + tr;
                float mu = mean_[mi][h], rs = rstd[mi][h];
                float y0 = (acc[mi][nb][2 * h]     - mu) * rs * g0 + t0;
                float y1 = (acc[mi][nb][2 * h + 1] - mu) * rs * g1 + t1;
                float o0 = y0 * normcdff(y0);
                float o1 = y1 * normcdff(y1);
                if (MODE == 0) {
                    *(__half2*)(Anext + (size_t)rg * 512 + 256 + cg) = __floats2half2_rn(o0, o1);
                } else {
                    if (rg < N_NODES) {
                        int bidx = batch[rg];
                        float inv = g_binv[bidx];
                        atomicAdd(&out[bidx * D_OUT + cg],     o0 * inv);
                        atomicAdd(&out[bidx * D_OUT + cg + 1], o1 * inv);
                    }
                }
            }
    }
}

// ---------------- launch -----------------------------------------------------
extern "C" void kernel_launch(void* const* d_in, const int* in_sizes, int n_in,
                              void* d_out, int out_size) {
    const float* x     = (const float*)d_in[0];
    const int*   ei    = (const int*)d_in[1];
    const int*   src   = ei;
    const int*   dst   = ei + N_EDGES;
    const int*   batch = (const int*)d_in[2];
    const float* Wl1 = (const float*)d_in[3],  *Wr1 = (const float*)d_in[4];
    const float* b1  = (const float*)d_in[5],  *g1  = (const float*)d_in[6],  *bt1 = (const float*)d_in[7];
    const float* Wl2 = (const float*)d_in[8],  *Wr2 = (const float*)d_in[9];
    const float* b2  = (const float*)d_in[10], *g2  = (const float*)d_in[11], *bt2 = (const float*)d_in[12];
    const float* Wl3 = (const float*)d_in[13], *Wr3 = (const float*)d_in[14];
    const float* b3  = (const float*)d_in[15], *g3  = (const float*)d_in[16], *bt3 = (const float*)d_in[17];
    const float* Wl4 = (const float*)d_in[18], *Wr4 = (const float*)d_in[19];
    const float* b4  = (const float*)d_in[20], *g4  = (const float*)d_in[21], *bt4 = (const float*)d_in[22];
    float* out = (float*)d_out;

    __half *AA, *AB, *WtAll, *xc16, *Wt1;
    cudaGetSymbolAddress((void**)&AA,    g_AA);
    cudaGetSymbolAddress((void**)&AB,    g_AB);
    cudaGetSymbolAddress((void**)&WtAll, g_WtAll);
    cudaGetSymbolAddress((void**)&xc16,  g_xc16);
    cudaGetSymbolAddress((void**)&Wt1,   g_Wt1);
    __half* Wt2 = WtAll;
    __half* Wt3 = WtAll + (size_t)256 * 512;
    __half* Wt4 = WtAll + (size_t)512 * 512;

    const int TB = 256;
    int gridE  = (N_EDGES + TB - 1) / TB;
    int gridE4 = (N_EDGES / 4 + TB - 1) / TB;
    int gridWarpN = (N_NODES * 32 + TB - 1) / TB;
    int gridTiles = N_PAD / 128;   // 391

    const int SM1    = (16384 + 256 * 128) + 4096;
    const int SM256  = 3 * (16384 + 256 * 128) + 4096;
    const int SM128  = 3 * (16384 + 128 * 128) + 4096;
    cudaFuncSetAttribute(k_gemm_f<256, 0, 1>, cudaFuncAttributeMaxDynamicSharedMemorySize, SM1);
    cudaFuncSetAttribute(k_gemm_f<256, 0, 8>, cudaFuncAttributeMaxDynamicSharedMemorySize, SM256);
    cudaFuncSetAttribute(k_gemm_f<128, 1, 8>, cudaFuncAttributeMaxDynamicSharedMemorySize, SM128);

    // ---- setup (3 launches) ----
    k_hist<<<gridE4, TB>>>(dst, batch, out);
    k_scan<<<NB_SCAN, 1024>>>();
    k_scatterW<<<gridE, TB>>>(src, dst, Wl1, Wr1, Wl2, Wr2, Wl3, Wr3, Wl4, Wr4);

    // ---- layer 1: tensor-core K=64 (writes x-half of AA) ----
    k_agg15h<<<gridWarpN, TB>>>(x, xc16);
    k_gemm_f<256, 0, 1><<<gridTiles, 512, SM1>>>(xc16, Wt1, b1, g1, bt1, AA, nullptr, nullptr);

    // ---- layer 2 ----
    k_aggmean<<<gridWarpN, TB>>>(AA, AA);
    k_gemm_f<256, 0, 8><<<gridTiles, 512, SM256>>>(AA, Wt2, b2, g2, bt2, AB, nullptr, nullptr);

    // ---- layer 3 ----
    k_aggmean<<<gridWarpN, TB>>>(AB, AB);
    k_gemm_f<256, 0, 8><<<gridTiles, 512, SM256>>>(AB, Wt3, b3, g3, bt3, AA, nullptr, nullptr);

    // ---- layer 4: fused pool (pre-scaled by 1/count) ----
    k_aggmean<<<gridWarpN, TB>>>(AA, AA);
    k_gemm_f<128, 1, 8><<<gridTiles, 512, SM128>>>(AA, Wt4, b4, g4, bt4, nullptr, out, batch);
}

// round 17
// speedup vs baseline: 1.0128x; 1.0128x over previous
#include <cuda_runtime.h>
#include <cuda_bf16.h>
#include <cuda_fp16.h>
#include <math.h>
#include <stdint.h>

#define N_NODES 50000
#define N_PAD   50048            // 391 * 128
#define N_EDGES 800000
#define N_BATCH 128
#define D_IN    15
#define D_HID   256
#define D_OUT   128
#define LN_EPS  1e-5f
#define NB_SCAN 49               // ceil(50000/1024)

// ---------------- device scratch -------------------------------------------
// Activation rows: 512 fp16 = [mean(0:256) | x(256:512)]
__device__ __half g_AA[(size_t)N_PAD * 512];          // 51 MB
__device__ __half g_AB[(size_t)N_PAD * 512];          // 51 MB
__device__ __half g_WtAll[(256 + 256 + 128) * 512];   // W^T fp16, layers 2,3,4
__device__ __half g_xc16[(size_t)N_PAD * 64];         // layer-1 fp16 concat (K=64)
__device__ __half g_Wt1[256 * 64];                    // layer-1 W^T fp16
__device__ int   g_ssrc[N_EDGES];
__device__ int   g_off [N_NODES + 1];
__device__ int   g_cur [N_NODES];
__device__ int   g_deg [N_NODES];                     // self-cleaned in k_scan
__device__ int   g_bsum[64];
__device__ int   g_bcnt[N_BATCH];                     // self-cleaned in k_scan
__device__ float g_binv[N_BATCH];                     // 1/count per batch
__device__ unsigned int g_epoch;                      // monotonic barrier counter

// ---------------- PTX helpers ----------------------------------------------
__device__ __forceinline__ uint32_t smem_to_u32(const void* p) {
    uint32_t a;
    asm("{ .reg .u64 t; cvta.to.shared.u64 t, %1; cvt.u32.u64 %0, t; }" : "=r"(a) : "l"(p));
    return a;
}
#define CP16(dst, src) \
    asm volatile("cp.async.cg.shared.global [%0], [%1], 16;" :: "r"((uint32_t)(dst)), "l"(src) : "memory")
#define CP_COMMIT() asm volatile("cp.async.commit_group;" ::: "memory")
#define CP_WAIT(n)  asm volatile("cp.async.wait_group %0;" :: "n"(n) : "memory")
#define SWZ(b) ((b) ^ (((b) >> 3) & 0x70))
#define LDSM_X4(r0, r1, r2, r3, addr) \
    asm volatile("ldmatrix.sync.aligned.m8n8.x4.shared.b16 {%0,%1,%2,%3}, [%4];" \
                 : "=r"(r0), "=r"(r1), "=r"(r2), "=r"(r3) : "r"(addr))
#define MMA_F16(d, a, b0, b1) \
    asm volatile("mma.sync.aligned.m16n8k16.row.col.f32.f16.f16.f32 " \
                 "{%0,%1,%2,%3}, {%4,%5,%6,%7}, {%8,%9}, {%0,%1,%2,%3};" \
                 : "+f"((d)[0]), "+f"((d)[1]), "+f"((d)[2]), "+f"((d)[3]) \
                 : "r"((a)[0]), "r"((a)[1]), "r"((a)[2]), "r"((a)[3]), \
                   "r"(b0), "r"(b1))

// ---------------- setup kernels --------------------------------------------
// histograms (4 edges/thread for atomic MLP) + zero out
__global__ void k_hist(const int* __restrict__ dst, const int* __restrict__ batch,
                       float* __restrict__ out) {
    int i = blockIdx.x * blockDim.x + threadIdx.x;
    int e0 = i * 4;
    if (e0 + 3 < N_EDGES) {
        int d0 = dst[e0], d1 = dst[e0 + 1], d2 = dst[e0 + 2], d3 = dst[e0 + 3];
        atomicAdd(&g_deg[d0], 1);
        atomicAdd(&g_deg[d1], 1);
        atomicAdd(&g_deg[d2], 1);
        atomicAdd(&g_deg[d3], 1);
    } else {
        for (int e = e0; e < N_EDGES; e++) atomicAdd(&g_deg[dst[e]], 1);
    }
    if (i < N_NODES) atomicAdd(&g_bcnt[batch[i]], 1);
    if (i < N_BATCH * D_OUT) out[i] = 0.f;
}

// merged scan: per-block scan + epoch-counter grid barrier + global prefix
__global__ void k_scan() {
    __shared__ int ws[32];
    __shared__ int sexcl;
    int tid = threadIdx.x, lane = tid & 31, wid = tid >> 5;
    int i = blockIdx.x * 1024 + tid;

    int v = 0;
    if (i < N_NODES) { v = g_deg[i]; g_deg[i] = 0; }
    int x = v;
    #pragma unroll
    for (int o = 1; o < 32; o <<= 1) {
        int t = __shfl_up_sync(0xffffffffu, x, o);
        if (lane >= o) x += t;
    }
    if (lane == 31) ws[wid] = x;
    __syncthreads();
    if (wid == 0) {
        int y = ws[lane];
        #pragma unroll
        for (int o = 1; o < 32; o <<= 1) {
            int t = __shfl_up_sync(0xffffffffu, y, o);
            if (lane >= o) y += t;
        }
        ws[lane] = y;
    }
    __syncthreads();
    int incl = x + (wid ? ws[wid - 1] : 0);
    int btotal = ws[31];
    if (tid == 1023) {
        g_bsum[blockIdx.x] = btotal;
        __threadfence();
    }
    __syncthreads();

    if (tid == 0) {
        unsigned t = atomicAdd(&g_epoch, 1u);
        unsigned target = (t / NB_SCAN + 1u) * NB_SCAN;
        while (atomicAdd(&g_epoch, 0u) < target) { }
        __threadfence();
    }
    __syncthreads();

    if (tid < 32) {
        int bv = (lane < NB_SCAN) ? g_bsum[lane] : 0;
        int bx = bv;
        #pragma unroll
        for (int o = 1; o < 32; o <<= 1) {
            int t = __shfl_up_sync(0xffffffffu, bx, o);
            if (lane >= o) bx += t;
        }
        int excl = bx - bv;
        int myexcl;
        if (blockIdx.x < 32) {
            myexcl = __shfl_sync(0xffffffffu, excl, blockIdx.x);
        } else {
            int base = __shfl_sync(0xffffffffu, bx, 31);
            int a = base;
            for (int b = 32; b < (int)blockIdx.x; b++) a += g_bsum[b];
            myexcl = a;
        }
        if (lane == 0) {
            sexcl = myexcl;
            if (blockIdx.x == NB_SCAN - 1) g_off[N_NODES] = myexcl + btotal;
        }
    }
    if (blockIdx.x == 0 && tid >= 128 && tid < 256) {
        int b = tid - 128;
        int c = g_bcnt[b];
        g_binv[b] = 1.f / (float)max(c, 1);
        g_bcnt[b] = 0;
    }
    __syncthreads();
    if (i < N_NODES) {
        int o = (incl - v) + sexcl;
        g_off[i] = o;
        g_cur[i] = o;
    }
}

// counting-sort scatter (1 edge/thread) + weight build merged
__global__ void k_scatterW(const int* __restrict__ src, const int* __restrict__ dst,
                           const float* __restrict__ Wl1, const float* __restrict__ Wr1,
                           const float* __restrict__ Wl2, const float* __restrict__ Wr2,
                           const float* __restrict__ Wl3, const float* __restrict__ Wr3,
                           const float* __restrict__ Wl4, const float* __restrict__ Wr4) {
    int e = blockIdx.x * blockDim.x + threadIdx.x;
    if (e < N_EDGES) {
        int p = atomicAdd(&g_cur[dst[e]], 1);
        g_ssrc[p] = src[e];
    }
    if (e < 344064) {
        int i = e;
        if (i < 16384) {                                 // Wt1 [256][64]
            int n = i >> 6, k = i & 63;
            float v = 0.f;
            if (k < D_IN)          v = Wl1[k * D_HID + n];
            else if (k < 2 * D_IN) v = Wr1[(k - D_IN) * D_HID + n];
            g_Wt1[i] = __float2half(v);
        } else {
            i -= 16384;
            const float *Wl, *Wr;
            __half* Wt;
            int ncols;
            if (i < 131072)      { Wl = Wl2; Wr = Wr2; Wt = g_WtAll;                     ncols = D_HID; }
            else if (i < 262144) { Wl = Wl3; Wr = Wr3; Wt = g_WtAll + (size_t)256 * 512; ncols = D_HID; i -= 131072; }
            else                 { Wl = Wl4; Wr = Wr4; Wt = g_WtAll + (size_t)512 * 512; ncols = D_OUT; i -= 262144; }
            int n = i / 512, k = i - n * 512;
            float v = (k < 256) ? Wl[k * ncols + n] : Wr[(k - 256) * ncols + n];
            Wt[n * 512 + k] = __float2half(v);
        }
    }
}

// ---------------- layer-1 concat: HALF-WARP per node (2 nodes/warp) ----------
__global__ void k_agg15h(const float* __restrict__ x, __half* __restrict__ xc) {
    int warp = (blockIdx.x * blockDim.x + threadIdx.x) >> 5;
    int lane = threadIdx.x & 31;
    int node = warp * 2 + (lane >> 4);      // lanes 0-15 -> node 2w, 16-31 -> 2w+1
    int fl = lane & 15;                     // feature lane, active when < 15
    if (node >= N_NODES) return;
    int s = g_off[node], e = g_off[node + 1];
    float acc = 0.f;
    int i = s;
    for (; i + 3 < e; i += 4) {
        int s0 = g_ssrc[i], s1 = g_ssrc[i + 1], s2 = g_ssrc[i + 2], s3 = g_ssrc[i + 3];
        float v0 = 0.f, v1 = 0.f, v2 = 0.f, v3 = 0.f;
        if (fl < D_IN) {
            v0 = x[s0 * D_IN + fl];
            v1 = x[s1 * D_IN + fl];
            v2 = x[s2 * D_IN + fl];
            v3 = x[s3 * D_IN + fl];
        }
        acc += (v0 + v1) + (v2 + v3);
    }
    for (; i < e; i++) {
        int sn = g_ssrc[i];
        if (fl < D_IN) acc += x[sn * D_IN + fl];
    }
    float inv = 1.f / (float)max(e - s, 1);
    __half* row = xc + (size_t)node * 64;
    if (fl < D_IN) {
        row[fl]        = __float2half(acc * inv);
        row[D_IN + fl] = __float2half(x[node * D_IN + fl]);
    }
}

// ---------------- mean aggregation ------------------------------------------
__device__ __forceinline__ void acch(float* a, uint4 h) {
    const __half2* hp = (const __half2*)&h;
    #pragma unroll
    for (int p = 0; p < 4; p++) {
        float2 f = __half22float2(hp[p]);
        a[2 * p]     += f.x;
        a[2 * p + 1] += f.y;
    }
}
__global__ void k_aggmean(const __half* __restrict__ Ain, __half* __restrict__ Am) {
    int warp = (blockIdx.x * blockDim.x + threadIdx.x) >> 5;
    if (warp >= N_NODES) return;
    int lane = threadIdx.x & 31;
    int s = g_off[warp], e = g_off[warp + 1];
    float acc[8];
    #pragma unroll
    for (int j = 0; j < 8; j++) acc[j] = 0.f;
    int i = s;
    for (; i + 7 < e; i += 8) {
        uint4 v[8];
        #pragma unroll
        for (int u = 0; u < 8; u++) {
            int sn = g_ssrc[i + u];
            v[u] = *(const uint4*)(Ain + (size_t)sn * 512 + 256 + lane * 8);
        }
        #pragma unroll
        for (int u = 0; u < 8; u++) acch(acc, v[u]);
    }
    for (; i + 3 < e; i += 4) {
        uint4 v[4];
        #pragma unroll
        for (int u = 0; u < 4; u++) {
            int sn = g_ssrc[i + u];
            v[u] = *(const uint4*)(Ain + (size_t)sn * 512 + 256 + lane * 8);
        }
        #pragma unroll
        for (int u = 0; u < 4; u++) acch(acc, v[u]);
    }
    for (; i < e; i++) {
        int sn = g_ssrc[i];
        uint4 v = *(const uint4*)(Ain + (size_t)sn * 512 + 256 + lane * 8);
        acch(acc, v);
    }
    float inv = 1.f / (float)max(e - s, 1);
    __half2 o[4];
    #pragma unroll
    for (int p = 0; p < 4; p++)
        o[p] = __floats2half2_rn(acc[2 * p] * inv, acc[2 * p + 1] * inv);
    *(uint4*)(Am + (size_t)warp * 512 + lane * 8) = *(uint4*)o;
}

// ---------------- fused fp16 tensor-core GEMM + bias + LN + GELU -------------
template<int NT, int MODE, int NC>
__global__ __launch_bounds__(512)
void k_gemm_f(const __half* __restrict__ A, const __half* __restrict__ Wt,
              const float* __restrict__ bias, const float* __restrict__ gam,
              const float* __restrict__ bet, __half* __restrict__ Anext,
              float* __restrict__ out, const int* __restrict__ batch) {
    extern __shared__ char smem[];
    uint32_t sb = smem_to_u32(smem);
    constexpr int K = NC * 64;
    constexpr int BBYTES = NT * 128;
    constexpr int STAGE = 16384 + BBYTES;
    constexpr int NSTG = (NC >= 3) ? 3 : ((NC >= 2) ? 2 : 1);
    constexpr int NB = NT / 32;
    constexpr int NB4 = NT / 64;
    constexpr int BAND = NT / 4;
    float2* red = (float2*)(smem + NSTG * STAGE);

    int tid = threadIdx.x, lane = tid & 31, warp = tid >> 5;
    int warp_m = warp & 3, warp_n = warp >> 2;
    int row0 = blockIdx.x * 128;

    float acc[2][NB][4];
    #pragma unroll
    for (int mi = 0; mi < 2; mi++)
        #pragma unroll
        for (int nb = 0; nb < NB; nb++)
            #pragma unroll
            for (int r = 0; r < 4; r++) acc[mi][nb][r] = 0.f;

    auto issue = [&](int c, int s) {
        uint32_t dA = sb + s * STAGE;
        uint32_t dB = dA + 16384;
        const __half* pa = A + (size_t)row0 * K + c * 64;
        const __half* pb = Wt + c * 64;
        #pragma unroll
        for (int i = 0; i < 2; i++) {
            int t = tid + i * 512;
            int r = t >> 3, seg = t & 7;
            CP16(dA + SWZ(r * 128 + seg * 16), pa + (size_t)r * K + seg * 8);
        }
        #pragma unroll
        for (int i = 0; i < NB4; i++) {
            int t = tid + i * 512;
            int r = t >> 3, seg = t & 7;
            CP16(dB + SWZ(r * 128 + seg * 16), pb + (size_t)r * K + seg * 8);
        }
        CP_COMMIT();
    };

    issue(0, 0);
    if (NC > 1) issue(1, 1 % NSTG);
    for (int c = 0; c < NC; c++) {
        int s = c % NSTG;
        if (c + 2 < NC) { issue(c + 2, (c + 2) % NSTG); CP_WAIT(2); }
        else if (c + 1 < NC) { CP_WAIT(1); }
        else { CP_WAIT(0); }
        __syncthreads();
        uint32_t sA = sb + s * STAGE, sB = sA + 16384;
        #pragma unroll
        for (int kk = 0; kk < 64; kk += 16) {
            uint32_t a[2][4], b[NB4][4];
            #pragma unroll
            for (int mi = 0; mi < 2; mi++) {
                int r = warp_m * 32 + mi * 16 + (lane & 15);
                int cb = (kk + (lane >> 4) * 8) * 2;
                LDSM_X4(a[mi][0], a[mi][1], a[mi][2], a[mi][3], sA + SWZ(r * 128 + cb));
            }
            #pragma unroll
            for (int nb4 = 0; nb4 < NB4; nb4++) {
                int g = lane >> 3;
                int n = warp_n * BAND + nb4 * 16 + (lane & 7) + (g >> 1) * 8;
                int kb = (kk + (g & 1) * 8) * 2;
                LDSM_X4(b[nb4][0], b[nb4][1], b[nb4][2], b[nb4][3], sB + SWZ(n * 128 + kb));
            }
            #pragma unroll
            for (int mi = 0; mi < 2; mi++)
                #pragma unroll
                for (int nb = 0; nb < NB; nb++) {
                    uint32_t b0 = b[nb >> 1][(nb & 1) * 2];
                    uint32_t b1 = b[nb >> 1][(nb & 1) * 2 + 1];
                    MMA_F16(acc[mi][nb], a[mi], b0, b1);
                }
        }
        __syncthreads();
    }

    // ---- epilogue: bias + LN + GELU + output ----
    int tr = lane >> 2, tc = lane & 3;
    #pragma unroll
    for (int nb = 0; nb < NB; nb++) {
        int cg = warp_n * BAND + nb * 8 + tc * 2;
        float bx = bias[cg], by = bias[cg + 1];
        #pragma unroll
        for (int mi = 0; mi < 2; mi++) {
            acc[mi][nb][0] += bx; acc[mi][nb][1] += by;
            acc[mi][nb][2] += bx; acc[mi][nb][3] += by;
        }
    }
    float ss[2][2], qq[2][2];
    #pragma unroll
    for (int mi = 0; mi < 2; mi++)
        #pragma unroll
        for (int h = 0; h < 2; h++) {
            float s = 0.f, q = 0.f;
            #pragma unroll
            for (int nb = 0; nb < NB; nb++) {
                float v0 = acc[mi][nb][2 * h], v1 = acc[mi][nb][2 * h + 1];
                s += v0 + v1; q += v0 * v0 + v1 * v1;
            }
            s += __shfl_xor_sync(0xffffffffu, s, 1);
            q += __shfl_xor_sync(0xffffffffu, q, 1);
            s += __shfl_xor_sync(0xffffffffu, s, 2);
            q += __shfl_xor_sync(0xffffffffu, q, 2);
            ss[mi][h] = s; qq[mi][h] = q;
        }
    if (tc == 0) {
        #pragma unroll
        for (int mi = 0; mi < 2; mi++)
            #pragma unroll
            for (int h = 0; h < 2; h++)
                red[warp_n * 128 + warp_m * 32 + mi * 16 + h * 8 + tr] =
                    make_float2(ss[mi][h], qq[mi][h]);
    }
    __syncthreads();
    float mean_[2][2], rstd[2][2];
    #pragma unroll
    for (int mi = 0; mi < 2; mi++)
        #pragma unroll
        for (int h = 0; h < 2; h++) {
            int rloc = warp_m * 32 + mi * 16 + h * 8 + tr;
            float S = 0.f, Q = 0.f;
            #pragma unroll
            for (int wn = 0; wn < 4; wn++) {
                float2 p = red[wn * 128 + rloc];
                S += p.x; Q += p.y;
            }
            float mu = S * (1.f / NT);
            float var = fmaxf(Q * (1.f / NT) - mu * mu, 0.f);
            mean_[mi][h] = mu;
            rstd[mi][h] = rsqrtf(var + LN_EPS);
        }
    #pragma unroll
    for (int nb = 0; nb < NB; nb++) {
        int cg = warp_n * BAND + nb * 8 + tc * 2;
        float g0 = gam[cg], g1 = gam[cg + 1];
        float t0 = bet[cg], t1 = bet[cg + 1];
        #pragma unroll
        for (int mi = 0; mi < 2; mi++)
            #pragma unroll
            for (int h = 0; h < 2; h++) {
                int rg = row0 + warp_m * 32 + mi * 16 + h * 8 + tr;
                float mu = mean_[mi][h], rs = rstd[mi][h];
                float y0 = (acc[mi][nb][2 * h]     - mu) * rs * g0 + t0;
                float y1 = (acc[mi][nb][2 * h + 1] - mu) * rs * g1 + t1;
                float o0 = y0 * normcdff(y0);
                float o1 = y1 * normcdff(y1);
                if (MODE == 0) {
                    *(__half2*)(Anext + (size_t)rg * 512 + 256 + cg) = __floats2half2_rn(o0, o1);
                } else {
                    if (rg < N_NODES) {
                        int bidx = batch[rg];
                        float inv = g_binv[bidx];
                        atomicAdd(&out[bidx * D_OUT + cg],     o0 * inv);
                        atomicAdd(&out[bidx * D_OUT + cg + 1], o1 * inv);
                    }
                }
            }
    }
}

// ---------------- launch -----------------------------------------------------
extern "C" void kernel_launch(void* const* d_in, const int* in_sizes, int n_in,
                              void* d_out, int out_size) {
    const float* x     = (const float*)d_in[0];
    const int*   ei    = (const int*)d_in[1];
    const int*   src   = ei;
    const int*   dst   = ei + N_EDGES;
    const int*   batch = (const int*)d_in[2];
    const float* Wl1 = (const float*)d_in[3],  *Wr1 = (const float*)d_in[4];
    const float* b1  = (const float*)d_in[5],  *g1  = (const float*)d_in[6],  *bt1 = (const float*)d_in[7];
    const float* Wl2 = (const float*)d_in[8],  *Wr2 = (const float*)d_in[9];
    const float* b2  = (const float*)d_in[10], *g2  = (const float*)d_in[11], *bt2 = (const float*)d_in[12];
    const float* Wl3 = (const float*)d_in[13], *Wr3 = (const float*)d_in[14];
    const float* b3  = (const float*)d_in[15], *g3  = (const float*)d_in[16], *bt3 = (const float*)d_in[17];
    const float* Wl4 = (const float*)d_in[18], *Wr4 = (const float*)d_in[19];
    const float* b4  = (const float*)d_in[20], *g4  = (const float*)d_in[21], *bt4 = (const float*)d_in[22];
    float* out = (float*)d_out;

    __half *AA, *AB, *WtAll, *xc16, *Wt1;
    cudaGetSymbolAddress((void**)&AA,    g_AA);
    cudaGetSymbolAddress((void**)&AB,    g_AB);
    cudaGetSymbolAddress((void**)&WtAll, g_WtAll);
    cudaGetSymbolAddress((void**)&xc16,  g_xc16);
    cudaGetSymbolAddress((void**)&Wt1,   g_Wt1);
    __half* Wt2 = WtAll;
    __half* Wt3 = WtAll + (size_t)256 * 512;
    __half* Wt4 = WtAll + (size_t)512 * 512;

    const int TB = 256;
    int gridE  = (N_EDGES + TB - 1) / TB;
    int gridE4 = (N_EDGES / 4 + TB - 1) / TB;
    int gridWarpN = (N_NODES * 32 + TB - 1) / TB;
    int gridHalf  = ((N_NODES + 1) / 2 * 32 + TB - 1) / TB;   // 2 nodes per warp
    int gridTiles = N_PAD / 128;   // 391

    const int SM1    = (16384 + 256 * 128) + 4096;
    const int SM256  = 3 * (16384 + 256 * 128) + 4096;
    const int SM128  = 3 * (16384 + 128 * 128) + 4096;
    cudaFuncSetAttribute(k_gemm_f<256, 0, 1>, cudaFuncAttributeMaxDynamicSharedMemorySize, SM1);
    cudaFuncSetAttribute(k_gemm_f<256, 0, 8>, cudaFuncAttributeMaxDynamicSharedMemorySize, SM256);
    cudaFuncSetAttribute(k_gemm_f<128, 1, 8>, cudaFuncAttributeMaxDynamicSharedMemorySize, SM128);

    // ---- setup (3 launches) ----
    k_hist<<<gridE4, TB>>>(dst, batch, out);
    k_scan<<<NB_SCAN, 1024>>>();
    k_scatterW<<<gridE, TB>>>(src, dst, Wl1, Wr1, Wl2, Wr2, Wl3, Wr3, Wl4, Wr4);

    // ---- layer 1: tensor-core K=64 (writes x-half of AA) ----
    k_agg15h<<<gridHalf, TB>>>(x, xc16);
    k_gemm_f<256, 0, 1><<<gridTiles, 512, SM1>>>(xc16, Wt1, b1, g1, bt1, AA, nullptr, nullptr);

    // ---- layer 2 ----
    k_aggmean<<<gridWarpN, TB>>>(AA, AA);
    k_gemm_f<256, 0, 8><<<gridTiles, 512, SM256>>>(AA, Wt2, b2, g2, bt2, AB, nullptr, nullptr);

    // ---- layer 3 ----
    k_aggmean<<<gridWarpN, TB>>>(AB, AB);
    k_gemm_f<256, 0, 8><<<gridTiles, 512, SM256>>>(AB, Wt3, b3, g3, bt3, AA, nullptr, nullptr);

    // ---- layer 4: fused pool (pre-scaled by 1/count) ----
    k_aggmean<<<gridWarpN, TB>>>(AA, AA);
    k_gemm_f<128, 1, 8><<<gridTiles, 512, SM128>>>(AA, Wt4, b4, g4, bt4, nullptr, out, batch);
}